// round 7
// baseline (speedup 1.0000x reference)
#include <cuda_runtime.h>

// Problem constants
#define Bn 32
#define Cc 3
#define Hd 384
#define Wd 640

// Tiling
#define TW 128      // output cols per block
#define TH 16       // output rows per block
#define PW 130      // padded cols loaded (TW + 2)
#define PWs 132     // smem row stride (in float2)
#define PH 18       // padded rows loaded (TH + 2)
#define RPT 8       // rows per thread (TH / 2)

__device__ __forceinline__ int reflect1(int i, int n) {
    // jnp.pad mode='reflect' with pad=1: -1 -> 1, n -> n-2
    if (i < 0) i = -i;
    if (i >= n) i = 2 * n - 2 - i;
    return i;
}

__global__ __launch_bounds__(256)
void recon_loss_kernel(const float* __restrict__ X,
                       const float* __restrict__ Y,
                       float* __restrict__ out) {
    // Interleaved (x, y) tile: halves LDS instruction count vs two arrays.
    __shared__ float2 s[PH][PWs];

    const int w0 = blockIdx.x * TW;
    const int h0 = blockIdx.y * TH;
    const int b  = blockIdx.z;
    const int tid = threadIdx.x;
    const int col = tid & (TW - 1);        // 0..127, consecutive within warp
    const int row_base = (tid >> 7) * RPT; // 0 or 8 (uniform per warp)

    const float inv9 = 1.0f / 9.0f;
    const float C1 = 6.5025f;    // (0.01*255)^2
    const float C2 = 58.5225f;   // (0.03*255)^2

    float ssim_acc[RPT];
    float l1_acc[RPT];
#pragma unroll
    for (int i = 0; i < RPT; i++) { ssim_acc[i] = 0.0f; l1_acc[i] = 0.0f; }

    for (int c = 0; c < Cc; c++) {
        const float* __restrict__ xb = X + (size_t)(b * Cc + c) * (Hd * Wd);
        const float* __restrict__ yb = Y + (size_t)(b * Cc + c) * (Hd * Wd);

        __syncthreads();   // protect smem from readers of previous channel

        // Cooperative load of reflect-padded tile (coalesced along rows).
        // PH*PW = 2340 elems -> ~10 iters of 256 threads (high MLP).
        for (int idx = tid; idx < PH * PW; idx += 256) {
            int i = idx / PW;
            int j = idx - i * PW;
            int gr = reflect1(h0 - 1 + i, Hd);
            int gc = reflect1(w0 - 1 + j, Wd);
            int g = gr * Wd + gc;
            s[i][j] = make_float2(xb[g], yb[g]);
        }
        __syncthreads();

        // Rolling horizontal row-sums (ring of 3) for 5 quantities + center vals
        float rs_x[3], rs_y[3], rs_xx[3], rs_yy[3], rs_xy[3];
        float cvx[3], cvy[3];

#pragma unroll
        for (int k = 0; k < 2; k++) {
            int pr = row_base + k;
            float2 v0 = s[pr][col], v1 = s[pr][col + 1], v2 = s[pr][col + 2];
            rs_x[k]  = v0.x + v1.x + v2.x;
            rs_y[k]  = v0.y + v1.y + v2.y;
            rs_xx[k] = v0.x * v0.x + v1.x * v1.x + v2.x * v2.x;
            rs_yy[k] = v0.y * v0.y + v1.y * v1.y + v2.y * v2.y;
            rs_xy[k] = v0.x * v0.y + v1.x * v1.y + v2.x * v2.y;
            cvx[k] = v1.x; cvy[k] = v1.y;
        }

#pragma unroll
        for (int h = 0; h < RPT; h++) {
            const int kn = (h + 2) % 3;   // slot for the new (bottom) row
            const int km = (h + 1) % 3;   // slot holding the center row
            int pr = row_base + h + 2;
            float2 v0 = s[pr][col], v1 = s[pr][col + 1], v2 = s[pr][col + 2];
            rs_x[kn]  = v0.x + v1.x + v2.x;
            rs_y[kn]  = v0.y + v1.y + v2.y;
            rs_xx[kn] = v0.x * v0.x + v1.x * v1.x + v2.x * v2.x;
            rs_yy[kn] = v0.y * v0.y + v1.y * v1.y + v2.y * v2.y;
            rs_xy[kn] = v0.x * v0.y + v1.x * v1.y + v2.x * v2.y;
            cvx[kn] = v1.x; cvy[kn] = v1.y;

            // 3x3 window sums = sum of the three ring entries
            float s_x  = rs_x[0]  + rs_x[1]  + rs_x[2];
            float s_y  = rs_y[0]  + rs_y[1]  + rs_y[2];
            float s_xx = rs_xx[0] + rs_xx[1] + rs_xx[2];
            float s_yy = rs_yy[0] + rs_yy[1] + rs_yy[2];
            float s_xy = rs_xy[0] + rs_xy[1] + rs_xy[2];

            float mu_x = s_x * inv9;
            float mu_y = s_y * inv9;
            // faithful to reference: sig = E[v^2] - mu (NOT mu^2)
            float sig_x  = s_xx * inv9 - mu_x;
            float sig_y  = s_yy * inv9 - mu_y;
            float sig_xy = s_xy * inv9 - mu_x * mu_y;

            float num = (2.0f * mu_x * mu_y + C1) * (2.0f * sig_xy + C2);
            float den = (mu_x * mu_x + mu_y * mu_y + C1) * (sig_x + sig_y + C2);
            float ns  = 0.5f * (1.0f - __fdividef(num, den));
            ns = fminf(fmaxf(ns, 0.0f), 1.0f);

            ssim_acc[h] += ns;
            l1_acc[h]   += fabsf(cvx[km] - cvy[km]);
        }
    }

    // Combine and write (coalesced per warp-row)
    float* __restrict__ ob = out + (size_t)b * Hd * Wd;
#pragma unroll
    for (int h = 0; h < RPT; h++) {
        int gr = h0 + row_base + h;
        // 0.5*ALPHA*mean_c(ssim) + (1-ALPHA)*mean_c(l1), ALPHA=0.85, mean over 3 ch
        ob[gr * Wd + w0 + col] =
            (0.425f * ssim_acc[h] + 0.15f * l1_acc[h]) * (1.0f / 3.0f);
    }
}

extern "C" void kernel_launch(void* const* d_in, const int* in_sizes, int n_in,
                              void* d_out, int out_size) {
    const float* X = (const float*)d_in[0];   // output
    const float* Y = (const float*)d_in[1];   // target
    float* O = (float*)d_out;

    dim3 grid(Wd / TW, Hd / TH, Bn);   // 5 x 24 x 32
    dim3 block(256);
    recon_loss_kernel<<<grid, block>>>(X, Y, O);
}

// round 8
// speedup vs baseline: 1.1305x; 1.1305x over previous
#include <cuda_runtime.h>

// Problem constants
#define Bn 32
#define Cc 3
#define Hd 384
#define Wd 640

// Tiling
#define TW 128      // output cols per block
#define TH 16       // output rows per block
#define PW 130      // padded cols (TW + 2)
#define PWs 132     // smem row stride (in float2)
#define PH 18       // padded rows (TH + 2)
#define RPT 8       // rows per thread (TH / 2)

__device__ __forceinline__ int reflect1(int i, int n) {
    // jnp.pad mode='reflect', pad=1: -1 -> 1, n -> n-2
    if (i < 0) i = -i;
    if (i >= n) i = 2 * n - 2 - i;
    return i;
}

__global__ __launch_bounds__(256)
void recon_loss_kernel(const float* __restrict__ X,
                       const float* __restrict__ Y,
                       float* __restrict__ out) {
    // Interleaved (x, y) tile: LDS.64 halves LDS instruction count.
    __shared__ float2 s[PH][PWs];

    const int w0 = blockIdx.x * TW;
    const int h0 = blockIdx.y * TH;
    const int b  = blockIdx.z;
    const int tid = threadIdx.x;
    const int col = tid & (TW - 1);        // 0..127
    const int row_base = (tid >> 7) * RPT; // 0 or 8

    // ---- load geometry: computed ONCE, reused for all 3 channels ----
    // Main map: thread covers (i = i0 + 2k, j = jm) for k = 0..8.
    const int i0 = tid >> 7;                       // 0 or 1
    const int jm = tid & 127;                      // padded col 0..127
    const int gcm = reflect1(w0 - 1 + jm, Wd);     // reflected global col
    const int rb  = h0 - 1 + i0;                   // base padded-row -> global row
    // Tail: 36 threads cover padded cols 128,129 for all 18 rows.
    const bool tail = tid < 36;
    const int ti  = tid >> 1;                      // 0..17
    const int tj  = 128 + (tid & 1);
    const int tg  = reflect1(h0 - 1 + ti, Hd) * Wd + reflect1(w0 - 1 + tj, Wd);

    // 81*C1 == 9*C2 == 526.7025 (since C2 = 9*C1)
    const float KC  = 526.7025f;
    const float KC9 = 4740.3225f;   // 81*C2

    float ssim_acc[RPT], l1_acc[RPT];
#pragma unroll
    for (int i = 0; i < RPT; i++) { ssim_acc[i] = 0.0f; l1_acc[i] = 0.0f; }

    for (int c = 0; c < Cc; c++) {
        const float* __restrict__ xb = X + (size_t)(b * Cc + c) * (Hd * Wd);
        const float* __restrict__ yb = Y + (size_t)(b * Cc + c) * (Hd * Wd);

        __syncthreads();   // protect smem from readers of previous channel

        // Cooperative load of reflect-padded tile: fixed (i,j) map, no division.
#pragma unroll
        for (int k = 0; k < 9; k++) {
            int gr = reflect1(rb + 2 * k, Hd);
            int g  = gr * Wd + gcm;
            s[i0 + 2 * k][jm] = make_float2(xb[g], yb[g]);
        }
        if (tail) s[ti][tj] = make_float2(xb[tg], yb[tg]);
        __syncthreads();

        // Rolling horizontal row-sums (ring of 3): 5 quantities + center diff
        float rs_x[3], rs_y[3], rs_xx[3], rs_yy[3], rs_xy[3], dv[3];

#pragma unroll
        for (int k = 0; k < 2; k++) {
            int pr = row_base + k;
            float2 v0 = s[pr][col], v1 = s[pr][col + 1], v2 = s[pr][col + 2];
            rs_x[k]  = v0.x + v1.x + v2.x;
            rs_y[k]  = v0.y + v1.y + v2.y;
            rs_xx[k] = v0.x * v0.x + v1.x * v1.x + v2.x * v2.x;
            rs_yy[k] = v0.y * v0.y + v1.y * v1.y + v2.y * v2.y;
            rs_xy[k] = v0.x * v0.y + v1.x * v1.y + v2.x * v2.y;
            dv[k]    = v1.x - v1.y;
        }

#pragma unroll
        for (int h = 0; h < RPT; h++) {
            const int kn = (h + 2) % 3;   // slot for the new (bottom) row
            const int km = (h + 1) % 3;   // slot holding the center row
            int pr = row_base + h + 2;
            float2 v0 = s[pr][col], v1 = s[pr][col + 1], v2 = s[pr][col + 2];
            rs_x[kn]  = v0.x + v1.x + v2.x;
            rs_y[kn]  = v0.y + v1.y + v2.y;
            rs_xx[kn] = v0.x * v0.x + v1.x * v1.x + v2.x * v2.x;
            rs_yy[kn] = v0.y * v0.y + v1.y * v1.y + v2.y * v2.y;
            rs_xy[kn] = v0.x * v0.y + v1.x * v1.y + v2.x * v2.y;
            dv[kn]    = v1.x - v1.y;

            // Raw 3x3 window sums
            float Sx  = rs_x[0]  + rs_x[1]  + rs_x[2];
            float Sy  = rs_y[0]  + rs_y[1]  + rs_y[2];
            float Sxx = rs_xx[0] + rs_xx[1] + rs_xx[2];
            float Syy = rs_yy[0] + rs_yy[1] + rs_yy[2];
            float Sxy = rs_xy[0] + rs_xy[1] + rs_xy[2];

            // Scaled-through SSIM (exact rearrangement; uses C2 = 9*C1):
            //   num/den = P*Q / (9*R*T)
            //   P = 2*Sx*Sy + 81C1, Q = 18*Sxy - 2*Sx*Sy + 81C2
            //   R = Sx^2 + Sy^2 + 81C1, T = Sxx + Syy - Sx - Sy + 9C2
            float t = Sx * Sy;
            float P = fmaf(2.0f, t, KC);
            float Q = fmaf(18.0f, Sxy, fmaf(-2.0f, t, KC9));
            float R = fmaf(Sx, Sx, fmaf(Sy, Sy, KC));
            float T = (Sxx + Syy) + (KC - (Sx + Sy));
            float ratio = __fdividef(P * Q, R * T);
            // ns = (1 - num/den)/2 = 0.5 - ratio/18
            float ns = fmaf(ratio, -(1.0f / 18.0f), 0.5f);
            ns = fminf(fmaxf(ns, 0.0f), 1.0f);

            ssim_acc[h] += ns;
            l1_acc[h]   += fabsf(dv[km]);
        }
    }

    // Combine and write (coalesced per warp-row)
    float* __restrict__ ob = out + (size_t)b * Hd * Wd;
#pragma unroll
    for (int h = 0; h < RPT; h++) {
        int gr = h0 + row_base + h;
        // 0.5*ALPHA*mean_c(ssim) + (1-ALPHA)*mean_c(l1), ALPHA=0.85, 3 channels
        ob[gr * Wd + w0 + col] =
            (0.425f * ssim_acc[h] + 0.15f * l1_acc[h]) * (1.0f / 3.0f);
    }
}

extern "C" void kernel_launch(void* const* d_in, const int* in_sizes, int n_in,
                              void* d_out, int out_size) {
    const float* X = (const float*)d_in[0];   // output
    const float* Y = (const float*)d_in[1];   // target
    float* O = (float*)d_out;

    dim3 grid(Wd / TW, Hd / TH, Bn);   // 5 x 24 x 32
    dim3 block(256);
    recon_loss_kernel<<<grid, block>>>(X, Y, O);
}

// round 9
// speedup vs baseline: 1.3468x; 1.1913x over previous
#include <cuda_runtime.h>

// Problem constants
#define Bn 32
#define Cc 3
#define Hd 384
#define Wd 640

// Tiling
#define TW 128      // output cols per block
#define TH 16       // output rows per block
#define PW 130      // padded cols (TW + 2)
#define PWs 132     // smem row stride (in float2)
#define PH 18       // padded rows (TH + 2)
#define RPT 8       // rows per thread (TH / 2)

__device__ __forceinline__ int reflect1(int i, int n) {
    // jnp.pad mode='reflect', pad=1: -1 -> 1, n -> n-2
    if (i < 0) i = -i;
    if (i >= n) i = 2 * n - 2 - i;
    return i;
}

__global__ __launch_bounds__(256, 3)
void recon_loss_kernel(const float* __restrict__ X,
                       const float* __restrict__ Y,
                       float* __restrict__ out) {
    // Interleaved (x, y) tile: LDS.64 halves LDS instruction count.
    __shared__ float2 s[PH][PWs];

    const int w0 = blockIdx.x * TW;
    const int h0 = blockIdx.y * TH;
    const int b  = blockIdx.z;
    const int tid = threadIdx.x;
    const int col = tid & (TW - 1);        // 0..127
    const int row_base = (tid >> 7) * RPT; // 0 or 8

    // ---- load geometry: computed ONCE, reused for all 3 channels ----
    // Main map: thread covers (i = i0 + 2k, j = jm) for k = 0..8.
    const int i0 = tid >> 7;                       // 0 or 1
    const int jm = tid & 127;                      // padded col 0..127
    const int gcm = reflect1(w0 - 1 + jm, Wd);     // reflected global col
    const int rb  = h0 - 1 + i0;                   // base padded-row -> global row
    // Tail: 36 threads cover padded cols 128,129 for all 18 rows.
    const bool tail = tid < 36;
    const int ti  = tid >> 1;                      // 0..17
    const int tj  = 128 + (tid & 1);
    const int tg  = reflect1(h0 - 1 + ti, Hd) * Wd + reflect1(w0 - 1 + tj, Wd);

    // 81*C1 == 9*C2 == 526.7025 (since C2 = 9*C1)
    const float KC  = 526.7025f;
    const float KC9 = 4740.3225f;   // 81*C2

    // Single merged accumulator: 0.425*sum(ns) + 0.15*sum(|dv|)
    float acc[RPT];
#pragma unroll
    for (int i = 0; i < RPT; i++) acc[i] = 0.0f;

    for (int c = 0; c < Cc; c++) {
        const float* __restrict__ xb = X + (size_t)(b * Cc + c) * (Hd * Wd);
        const float* __restrict__ yb = Y + (size_t)(b * Cc + c) * (Hd * Wd);

        __syncthreads();   // protect smem from readers of previous channel

        // Cooperative load of reflect-padded tile: fixed (i,j) map, no division.
#pragma unroll
        for (int k = 0; k < 9; k++) {
            int gr = reflect1(rb + 2 * k, Hd);
            int g  = gr * Wd + gcm;
            s[i0 + 2 * k][jm] = make_float2(xb[g], yb[g]);
        }
        if (tail) s[ti][tj] = make_float2(xb[tg], yb[tg]);
        __syncthreads();

        // Rolling horizontal row-sums (ring of 3):
        //   rs_x = sum x, rs_y = sum y, rs_q = sum (x^2 + y^2), rs_xy = sum x*y
        float rs_x[3], rs_y[3], rs_q[3], rs_xy[3], dv[3];

#pragma unroll
        for (int k = 0; k < 2; k++) {
            int pr = row_base + k;
            float2 v0 = s[pr][col], v1 = s[pr][col + 1], v2 = s[pr][col + 2];
            rs_x[k]  = v0.x + v1.x + v2.x;
            rs_y[k]  = v0.y + v1.y + v2.y;
            rs_q[k]  = v0.x * v0.x + v0.y * v0.y + v1.x * v1.x + v1.y * v1.y
                     + v2.x * v2.x + v2.y * v2.y;
            rs_xy[k] = v0.x * v0.y + v1.x * v1.y + v2.x * v2.y;
            dv[k]    = v1.x - v1.y;
        }

#pragma unroll
        for (int h = 0; h < RPT; h++) {
            const int kn = (h + 2) % 3;   // slot for the new (bottom) row
            const int km = (h + 1) % 3;   // slot holding the center row
            int pr = row_base + h + 2;
            float2 v0 = s[pr][col], v1 = s[pr][col + 1], v2 = s[pr][col + 2];
            rs_x[kn]  = v0.x + v1.x + v2.x;
            rs_y[kn]  = v0.y + v1.y + v2.y;
            rs_q[kn]  = v0.x * v0.x + v0.y * v0.y + v1.x * v1.x + v1.y * v1.y
                      + v2.x * v2.x + v2.y * v2.y;
            rs_xy[kn] = v0.x * v0.y + v1.x * v1.y + v2.x * v2.y;
            dv[kn]    = v1.x - v1.y;

            // Raw 3x3 window sums
            float Sx  = rs_x[0]  + rs_x[1]  + rs_x[2];
            float Sy  = rs_y[0]  + rs_y[1]  + rs_y[2];
            float Sq  = rs_q[0]  + rs_q[1]  + rs_q[2];   // Sxx + Syy
            float Sxy = rs_xy[0] + rs_xy[1] + rs_xy[2];

            // Scaled-through SSIM (exact rearrangement; uses C2 = 9*C1):
            //   P = 2*Sx*Sy + 81C1, Q = 18*Sxy - 2*Sx*Sy + 81C2
            //   R = Sx^2 + Sy^2 + 81C1, T = Sq - Sx - Sy + 9C2
            //   ns = 0.5 - (P*Q)/(R*T)/18
            float t = Sx * Sy;
            float P = fmaf(2.0f, t, KC);
            float Q = fmaf(18.0f, Sxy, fmaf(-2.0f, t, KC9));
            float R = fmaf(Sx, Sx, fmaf(Sy, Sy, KC));
            float T = Sq + (KC - (Sx + Sy));
            float ratio = __fdividef(P * Q, R * T);
            float ns = fmaf(ratio, -(1.0f / 18.0f), 0.5f);
            ns = fminf(fmaxf(ns, 0.0f), 1.0f);

            acc[h] = fmaf(0.425f, ns, fmaf(0.15f, fabsf(dv[km]), acc[h]));
        }
    }

    // Combine and write (coalesced per warp-row)
    float* __restrict__ ob = out + (size_t)b * Hd * Wd;
#pragma unroll
    for (int h = 0; h < RPT; h++) {
        int gr = h0 + row_base + h;
        ob[gr * Wd + w0 + col] = acc[h] * (1.0f / 3.0f);
    }
}

extern "C" void kernel_launch(void* const* d_in, const int* in_sizes, int n_in,
                              void* d_out, int out_size) {
    const float* X = (const float*)d_in[0];   // output
    const float* Y = (const float*)d_in[1];   // target
    float* O = (float*)d_out;

    dim3 grid(Wd / TW, Hd / TH, Bn);   // 5 x 24 x 32
    dim3 block(256);
    recon_loss_kernel<<<grid, block>>>(X, Y, O);
}